// round 6
// baseline (speedup 1.0000x reference)
#include <cuda_runtime.h>
#include <cuda_fp16.h>
#include <cstdint>

// Shape fixed by setup_inputs: B=1, H=8, N=4096, D=64, fp32 in/out.
#define HEADS 8
#define NSEQ  4096
#define DDIM  64
#define TM    128          // CTA tile rows (Q)
#define TN    64           // CTA tile cols (K)

// SW128 swizzle (Swizzle<3,4,3>) on byte offsets relative to a 1024B-aligned base.
#define SW128(off) ((off) ^ ((((uint32_t)(off)) >> 3) & 0x70))

__device__ float g_q2[HEADS * NSEQ];
__device__ float g_k2[HEADS * NSEQ];

// ---------------------------------------------------------------------------
// Kernel 1: per-row squared norms (fp32 exact).
// ---------------------------------------------------------------------------
__global__ void hept_norms_kernel(const float* __restrict__ q,
                                  const float* __restrict__ k) {
    int row = blockIdx.x * blockDim.x + threadIdx.x;
    if (row >= HEADS * NSEQ) return;
    const float* src = (blockIdx.y == 0) ? q : k;
    float*       dst = (blockIdx.y == 0) ? g_q2 : g_k2;
    const float4* p = reinterpret_cast<const float4*>(src + (size_t)row * DDIM);
    float s = 0.f;
#pragma unroll
    for (int i = 0; i < DDIM / 4; ++i) {
        float4 v = p[i];
        s += v.x * v.x + v.y * v.y + v.z * v.z + v.w * v.w;
    }
    dst[row] = s;
}

// ---------------------------------------------------------------------------
static __device__ __forceinline__ uint32_t smem_u32(const void* p) {
    uint32_t a;
    asm("{ .reg .u64 t; cvta.to.shared.u64 t, %1; cvt.u32.u64 %0, t; }"
        : "=r"(a) : "l"(p));
    return a;
}

#define LDMATRIX_X4(r0, r1, r2, r3, addr)                                     \
    asm volatile("ldmatrix.sync.aligned.m8n8.x4.shared.b16 {%0,%1,%2,%3}, [%4];" \
                 : "=r"(r0), "=r"(r1), "=r"(r2), "=r"(r3) : "r"(addr))

#define MMA_16816(c, a, b)                                                     \
    asm volatile("mma.sync.aligned.m16n8k16.row.col.f32.f16.f16.f32 "         \
                 "{%0,%1,%2,%3}, {%4,%5,%6,%7}, {%8,%9}, {%0,%1,%2,%3};"      \
                 : "+f"((c)[0]), "+f"((c)[1]), "+f"((c)[2]), "+f"((c)[3])     \
                 : "r"((a)[0]), "r"((a)[1]), "r"((a)[2]), "r"((a)[3]),        \
                   "r"((b)[0]), "r"((b)[1]))

// ---------------------------------------------------------------------------
// Kernel 2: HMMA fp16-split GEMM + exp epilogue.
// Grid (64, 32, 8), 128 threads (4 warps, 2m x 2n), warp tile 64x32,
// CTA tile 128x64. 4 CTAs/SM (regs<=128, smem 48KB) so independent CTAs
// overlap load/MMA/epilogue phases.
// dyn smem (1024-aligned): Qhi|Qlo (16KB each) | Khi|Klo (8KB each).
// ---------------------------------------------------------------------------
#define SM_QB   16384
#define SM_KB   8192
#define SM_ALLOC (2 * SM_QB + 2 * SM_KB + 1024)

__global__ __launch_bounds__(128, 4)
void hept_mma_kernel(const float* __restrict__ Q,
                     const float* __restrict__ K,
                     float* __restrict__ out) {
    extern __shared__ char smem_raw[];
    const uint32_t sbase = smem_u32(smem_raw);
    const uint32_t abase = (sbase + 1023u) & ~1023u;
    char* base = smem_raw + (abase - sbase);

    const uint32_t QHI = abase;
    const uint32_t QLO = abase + SM_QB;
    const uint32_t KHI = abase + 2 * SM_QB;
    const uint32_t KLO = abase + 2 * SM_QB + SM_KB;
    char* qhi = base;
    char* qlo = base + SM_QB;
    char* khi = base + 2 * SM_QB;
    char* klo = base + 2 * SM_QB + SM_KB;

    const int tid  = threadIdx.x;
    const int lane = tid & 31;
    const int wid  = tid >> 5;
    const int wm   = wid >> 1;          // 0..1 -> 64-row slab
    const int wn   = wid & 1;           // 0..1 -> 32-col slab
    const int h    = blockIdx.z;
    const int row0 = blockIdx.y * TM;
    const int col0 = blockIdx.x * TN;

    const float* Qh = Q + (size_t)h * NSEQ * DDIM;
    const float* Kh = K + (size_t)h * NSEQ * DDIM;

    // --- load fp32 tiles, split fp16 hi/lo, store swizzled.
    // Q: 128 rows x 16 float4 = 2048 / 128 thr = 16 iters.
#pragma unroll
    for (int it = 0; it < 16; ++it) {
        int idx = tid + it * 128;
        int r  = idx >> 4;
        int c4 = idx & 15;
        uint32_t off = SW128((uint32_t)(r * 128 + c4 * 8));
        float4 v = reinterpret_cast<const float4*>(Qh + (size_t)(row0 + r) * DDIM)[c4];
        __half2 h01 = __floats2half2_rn(v.x, v.y);
        __half2 h23 = __floats2half2_rn(v.z, v.w);
        float2 f01 = __half22float2(h01);
        float2 f23 = __half22float2(h23);
        __half2 l01 = __floats2half2_rn(v.x - f01.x, v.y - f01.y);
        __half2 l23 = __floats2half2_rn(v.z - f23.x, v.w - f23.y);
        *reinterpret_cast<uint2*>(qhi + off) =
            make_uint2(*reinterpret_cast<uint32_t*>(&h01), *reinterpret_cast<uint32_t*>(&h23));
        *reinterpret_cast<uint2*>(qlo + off) =
            make_uint2(*reinterpret_cast<uint32_t*>(&l01), *reinterpret_cast<uint32_t*>(&l23));
    }
    // K: 64 rows x 16 float4 = 1024 / 128 thr = 8 iters.
#pragma unroll
    for (int it = 0; it < 8; ++it) {
        int idx = tid + it * 128;
        int r  = idx >> 4;
        int c4 = idx & 15;
        uint32_t off = SW128((uint32_t)(r * 128 + c4 * 8));
        float4 w = reinterpret_cast<const float4*>(Kh + (size_t)(col0 + r) * DDIM)[c4];
        __half2 g01 = __floats2half2_rn(w.x, w.y);
        __half2 g23 = __floats2half2_rn(w.z, w.w);
        float2 e01 = __half22float2(g01);
        float2 e23 = __half22float2(g23);
        __half2 m01 = __floats2half2_rn(w.x - e01.x, w.y - e01.y);
        __half2 m23 = __floats2half2_rn(w.z - e23.x, w.w - e23.y);
        *reinterpret_cast<uint2*>(khi + off) =
            make_uint2(*reinterpret_cast<uint32_t*>(&g01), *reinterpret_cast<uint32_t*>(&g23));
        *reinterpret_cast<uint2*>(klo + off) =
            make_uint2(*reinterpret_cast<uint32_t*>(&m01), *reinterpret_cast<uint32_t*>(&m23));
    }
    __syncthreads();

    // --- lane-invariant ldmatrix address pieces.
    const int a_row = wm * 64 + (lane & 7) + ((lane >> 3) & 1) * 8;
    const int a_kof = ((lane >> 4) & 1) * 8;
    const uint32_t a_base_off = (uint32_t)(a_row * 128 + a_kof * 2);
    const int b_row = wn * 32 + (lane & 7) + ((lane >> 4) & 1) * 8;
    const int b_kof = ((lane >> 3) & 1) * 8;
    const uint32_t b_base_off = (uint32_t)(b_row * 128 + b_kof * 2);

    float acc[4][4][4];
#pragma unroll
    for (int mt = 0; mt < 4; ++mt)
#pragma unroll
        for (int nt = 0; nt < 4; ++nt)
#pragma unroll
            for (int i = 0; i < 4; ++i) acc[mt][nt][i] = 0.f;

#pragma unroll
    for (int ks = 0; ks < 4; ++ks) {
        uint32_t ahi[4][4], alo[4][4];
#pragma unroll
        for (int mt = 0; mt < 4; ++mt) {
            uint32_t off = SW128(a_base_off + (uint32_t)(mt * 2048 + ks * 32));
            LDMATRIX_X4(ahi[mt][0], ahi[mt][1], ahi[mt][2], ahi[mt][3], QHI + off);
            LDMATRIX_X4(alo[mt][0], alo[mt][1], alo[mt][2], alo[mt][3], QLO + off);
        }
        uint32_t bhi[4][2], blo[4][2];
        {
            uint32_t off = SW128(b_base_off + (uint32_t)(ks * 32));
            uint32_t r0, r1, r2, r3;
            LDMATRIX_X4(r0, r1, r2, r3, KHI + off);
            bhi[0][0] = r0; bhi[0][1] = r1; bhi[1][0] = r2; bhi[1][1] = r3;
            LDMATRIX_X4(r0, r1, r2, r3, KLO + off);
            blo[0][0] = r0; blo[0][1] = r1; blo[1][0] = r2; blo[1][1] = r3;
            off = SW128(b_base_off + (uint32_t)(2048 + ks * 32));
            LDMATRIX_X4(r0, r1, r2, r3, KHI + off);
            bhi[2][0] = r0; bhi[2][1] = r1; bhi[3][0] = r2; bhi[3][1] = r3;
            LDMATRIX_X4(r0, r1, r2, r3, KLO + off);
            blo[2][0] = r0; blo[2][1] = r1; blo[3][0] = r2; blo[3][1] = r3;
        }
        // 48 MMAs: hi*hi + lo*hi + hi*lo (lo*lo dropped, ~2^-22).
#pragma unroll
        for (int mt = 0; mt < 4; ++mt)
#pragma unroll
            for (int nt = 0; nt < 4; ++nt)
                MMA_16816(acc[mt][nt], ahi[mt], bhi[nt]);
#pragma unroll
        for (int mt = 0; mt < 4; ++mt)
#pragma unroll
            for (int nt = 0; nt < 4; ++nt)
                MMA_16816(acc[mt][nt], alo[mt], bhi[nt]);
#pragma unroll
        for (int mt = 0; mt < 4; ++mt)
#pragma unroll
            for (int nt = 0; nt < 4; ++nt)
                MMA_16816(acc[mt][nt], ahi[mt], blo[nt]);
    }

    // --- epilogue: d2 = q2 + k2 - 2*qk; out = exp(-0.5*max(d2,0))
    const float* q2p = g_q2 + h * NSEQ + row0;
    const float* k2p = g_k2 + h * NSEQ + col0;
    float* outh = out + (size_t)h * NSEQ * NSEQ;

#pragma unroll
    for (int mt = 0; mt < 4; ++mt) {
        const int rA = wm * 64 + mt * 16 + (lane >> 2);
        const int rB = rA + 8;
        const float q2a = q2p[rA];
        const float q2b = q2p[rB];
        float* orowA = outh + (size_t)(row0 + rA) * NSEQ + col0;
        float* orowB = outh + (size_t)(row0 + rB) * NSEQ + col0;
#pragma unroll
        for (int nt = 0; nt < 4; ++nt) {
            const int c = wn * 32 + nt * 8 + (lane & 3) * 2;
            const float k2a = k2p[c];
            const float k2b = k2p[c + 1];
            const float* v = acc[mt][nt];
            float2 oA, oB;
            oA.x = __expf(-0.5f * fmaxf(fmaf(-2.f, v[0], q2a + k2a), 0.f));
            oA.y = __expf(-0.5f * fmaxf(fmaf(-2.f, v[1], q2a + k2b), 0.f));
            oB.x = __expf(-0.5f * fmaxf(fmaf(-2.f, v[2], q2b + k2a), 0.f));
            oB.y = __expf(-0.5f * fmaxf(fmaf(-2.f, v[3], q2b + k2b), 0.f));
            *reinterpret_cast<float2*>(orowA + c) = oA;
            *reinterpret_cast<float2*>(orowB + c) = oB;
        }
    }
}

// ---------------------------------------------------------------------------
extern "C" void kernel_launch(void* const* d_in, const int* in_sizes, int n_in,
                              void* d_out, int out_size) {
    const float* q = (const float*)d_in[0];
    const float* k = (const float*)d_in[1];
    float* out = (float*)d_out;

    cudaFuncSetAttribute(hept_mma_kernel,
                         cudaFuncAttributeMaxDynamicSharedMemorySize, SM_ALLOC);

    dim3 ngrid((HEADS * NSEQ + 255) / 256, 2, 1);
    hept_norms_kernel<<<ngrid, 256>>>(q, k);

    dim3 mgrid(NSEQ / TN, NSEQ / TM, HEADS);
    hept_mma_kernel<<<mgrid, 128, SM_ALLOC>>>(q, k, out);
}

// round 7
// speedup vs baseline: 1.1480x; 1.1480x over previous
#include <cuda_runtime.h>
#include <cuda_fp16.h>
#include <cstdint>

// Shape fixed by setup_inputs: B=1, H=8, N=4096, D=64, fp32 in/out.
#define HEADS 8
#define NSEQ  4096
#define DDIM  64
#define TILE  128

// SW128 swizzle (Swizzle<3,4,3>) on byte offsets relative to a 1024B-aligned base.
#define SW128(off) ((off) ^ ((((uint32_t)(off)) >> 3) & 0x70))

__device__ float g_q2[HEADS * NSEQ];
__device__ float g_k2[HEADS * NSEQ];
// fp16 hi/lo split of Q and K, same [h, row, d] layout (4 MB each).
__device__ __half g_qhi[HEADS * NSEQ * DDIM];
__device__ __half g_qlo[HEADS * NSEQ * DDIM];
__device__ __half g_khi[HEADS * NSEQ * DDIM];
__device__ __half g_klo[HEADS * NSEQ * DDIM];

// ---------------------------------------------------------------------------
// Kernel 1: per-row squared norms (fp32 exact).
// ---------------------------------------------------------------------------
__global__ void hept_norms_kernel(const float* __restrict__ q,
                                  const float* __restrict__ k) {
    int row = blockIdx.x * blockDim.x + threadIdx.x;
    if (row >= HEADS * NSEQ) return;
    const float* src = (blockIdx.y == 0) ? q : k;
    float*       dst = (blockIdx.y == 0) ? g_q2 : g_k2;
    const float4* p = reinterpret_cast<const float4*>(src + (size_t)row * DDIM);
    float s = 0.f;
#pragma unroll
    for (int i = 0; i < DDIM / 4; ++i) {
        float4 v = p[i];
        s += v.x * v.x + v.y * v.y + v.z * v.z + v.w * v.w;
    }
    dst[row] = s;
}

// ---------------------------------------------------------------------------
// Kernel 1b: fp32 -> fp16 hi/lo split (elementwise, fully coalesced).
// One thread per 4 elements.
// ---------------------------------------------------------------------------
__global__ void hept_split_kernel(const float* __restrict__ q,
                                  const float* __restrict__ k) {
    const int total4 = HEADS * NSEQ * DDIM / 4;
    int i = blockIdx.x * blockDim.x + threadIdx.x;
    if (i >= total4) return;
    const float* src = (blockIdx.y == 0) ? q : k;
    __half* hi = (blockIdx.y == 0) ? g_qhi : g_khi;
    __half* lo = (blockIdx.y == 0) ? g_qlo : g_klo;

    float4 v = reinterpret_cast<const float4*>(src)[i];
    __half2 h01 = __floats2half2_rn(v.x, v.y);
    __half2 h23 = __floats2half2_rn(v.z, v.w);
    float2 f01 = __half22float2(h01);
    float2 f23 = __half22float2(h23);
    __half2 l01 = __floats2half2_rn(v.x - f01.x, v.y - f01.y);
    __half2 l23 = __floats2half2_rn(v.z - f23.x, v.w - f23.y);
    reinterpret_cast<uint2*>(hi)[i] =
        make_uint2(*reinterpret_cast<uint32_t*>(&h01), *reinterpret_cast<uint32_t*>(&h23));
    reinterpret_cast<uint2*>(lo)[i] =
        make_uint2(*reinterpret_cast<uint32_t*>(&l01), *reinterpret_cast<uint32_t*>(&l23));
}

// ---------------------------------------------------------------------------
static __device__ __forceinline__ uint32_t smem_u32(const void* p) {
    uint32_t a;
    asm("{ .reg .u64 t; cvta.to.shared.u64 t, %1; cvt.u32.u64 %0, t; }"
        : "=r"(a) : "l"(p));
    return a;
}

#define CP_ASYNC16(dst, src)                                                  \
    asm volatile("cp.async.cg.shared.global [%0], [%1], 16;"                  \
                 :: "r"(dst), "l"(src) : "memory")

#define LDMATRIX_X4(r0, r1, r2, r3, addr)                                     \
    asm volatile("ldmatrix.sync.aligned.m8n8.x4.shared.b16 {%0,%1,%2,%3}, [%4];" \
                 : "=r"(r0), "=r"(r1), "=r"(r2), "=r"(r3) : "r"(addr))

#define MMA_16816(c, a, b)                                                     \
    asm volatile("mma.sync.aligned.m16n8k16.row.col.f32.f16.f16.f32 "         \
                 "{%0,%1,%2,%3}, {%4,%5,%6,%7}, {%8,%9}, {%0,%1,%2,%3};"      \
                 : "+f"((c)[0]), "+f"((c)[1]), "+f"((c)[2]), "+f"((c)[3])     \
                 : "r"((a)[0]), "r"((a)[1]), "r"((a)[2]), "r"((a)[3]),        \
                   "r"((b)[0]), "r"((b)[1]))

// ---------------------------------------------------------------------------
// Kernel 2: HMMA fp16-split GEMM + exp epilogue.
// Grid (32, 32, 8), 256 threads (8 warps, 2m x 4n), warp tile 64x32.
// Tiles arrive pre-split as fp16 via cp.async.cg (no convert in hot kernel).
// Per K-step: 12 ldmatrix.x4 -> 48 MMAs (hi*hi, lo*hi, hi*lo). 2 CTAs/SM.
// dyn smem (1024-aligned): Qhi | Qlo | Khi | Klo, each 128x64 fp16 = 16KB.
// ---------------------------------------------------------------------------
#define SM_TILEB 16384
#define SM_ALLOC (4 * SM_TILEB + 1024)

__global__ __launch_bounds__(256, 2)
void hept_mma_kernel(float* __restrict__ out) {
    extern __shared__ char smem_raw[];
    const uint32_t sbase = smem_u32(smem_raw);
    const uint32_t abase = (sbase + 1023u) & ~1023u;

    const uint32_t QHI = abase;
    const uint32_t QLO = abase + SM_TILEB;
    const uint32_t KHI = abase + 2 * SM_TILEB;
    const uint32_t KLO = abase + 3 * SM_TILEB;

    const int tid  = threadIdx.x;
    const int lane = tid & 31;
    const int wid  = tid >> 5;
    const int wm   = wid >> 2;          // 0..1 -> 64-row slab
    const int wn   = wid & 3;           // 0..3 -> 32-col slab
    const int h    = blockIdx.z;
    const int row0 = blockIdx.y * TILE;
    const int col0 = blockIdx.x * TILE;

    const __half* srcs[4] = {
        g_qhi + ((size_t)h * NSEQ + row0) * DDIM,
        g_qlo + ((size_t)h * NSEQ + row0) * DDIM,
        g_khi + ((size_t)h * NSEQ + col0) * DDIM,
        g_klo + ((size_t)h * NSEQ + col0) * DDIM,
    };

    // --- async load: 4 arrays x 128 rows x 8 chunks(16B) = 4096 chunks,
    // 16 per thread. Swizzled smem dst, contiguous gmem src.
#pragma unroll
    for (int it = 0; it < 16; ++it) {
        int idx  = tid + it * 256;
        int arr  = idx >> 10;           // 0..3
        int cidx = idx & 1023;
        int r    = cidx >> 3;           // row in tile
        int c16  = cidx & 7;            // 16B chunk in row
        uint32_t dst = abase + (uint32_t)arr * SM_TILEB
                     + SW128((uint32_t)(r * 128 + c16 * 16));
        const __half* src = srcs[arr] + (size_t)r * DDIM + c16 * 8;
        CP_ASYNC16(dst, src);
    }
    asm volatile("cp.async.commit_group;" ::: "memory");
    asm volatile("cp.async.wait_group 0;" ::: "memory");
    __syncthreads();

    // --- lane-invariant ldmatrix address pieces.
    const int a_row = wm * 64 + (lane & 7) + ((lane >> 3) & 1) * 8;
    const int a_kof = ((lane >> 4) & 1) * 8;
    const uint32_t a_base_off = (uint32_t)(a_row * 128 + a_kof * 2);
    const int b_row = wn * 32 + (lane & 7) + ((lane >> 4) & 1) * 8;
    const int b_kof = ((lane >> 3) & 1) * 8;
    const uint32_t b_base_off = (uint32_t)(b_row * 128 + b_kof * 2);

    float acc[4][4][4];
#pragma unroll
    for (int mt = 0; mt < 4; ++mt)
#pragma unroll
        for (int nt = 0; nt < 4; ++nt)
#pragma unroll
            for (int i = 0; i < 4; ++i) acc[mt][nt][i] = 0.f;

#pragma unroll
    for (int ks = 0; ks < 4; ++ks) {
        uint32_t ahi[4][4], alo[4][4];
#pragma unroll
        for (int mt = 0; mt < 4; ++mt) {
            uint32_t off = SW128(a_base_off + (uint32_t)(mt * 2048 + ks * 32));
            LDMATRIX_X4(ahi[mt][0], ahi[mt][1], ahi[mt][2], ahi[mt][3], QHI + off);
            LDMATRIX_X4(alo[mt][0], alo[mt][1], alo[mt][2], alo[mt][3], QLO + off);
        }
        uint32_t bhi[4][2], blo[4][2];
        {
            uint32_t off = SW128(b_base_off + (uint32_t)(ks * 32));
            uint32_t r0, r1, r2, r3;
            LDMATRIX_X4(r0, r1, r2, r3, KHI + off);
            bhi[0][0] = r0; bhi[0][1] = r1; bhi[1][0] = r2; bhi[1][1] = r3;
            LDMATRIX_X4(r0, r1, r2, r3, KLO + off);
            blo[0][0] = r0; blo[0][1] = r1; blo[1][0] = r2; blo[1][1] = r3;
            off = SW128(b_base_off + (uint32_t)(2048 + ks * 32));
            LDMATRIX_X4(r0, r1, r2, r3, KHI + off);
            bhi[2][0] = r0; bhi[2][1] = r1; bhi[3][0] = r2; bhi[3][1] = r3;
            LDMATRIX_X4(r0, r1, r2, r3, KLO + off);
            blo[2][0] = r0; blo[2][1] = r1; blo[3][0] = r2; blo[3][1] = r3;
        }
        // 48 MMAs: hi*hi + lo*hi + hi*lo (lo*lo dropped, ~2^-22).
#pragma unroll
        for (int mt = 0; mt < 4; ++mt)
#pragma unroll
            for (int nt = 0; nt < 4; ++nt)
                MMA_16816(acc[mt][nt], ahi[mt], bhi[nt]);
#pragma unroll
        for (int mt = 0; mt < 4; ++mt)
#pragma unroll
            for (int nt = 0; nt < 4; ++nt)
                MMA_16816(acc[mt][nt], alo[mt], bhi[nt]);
#pragma unroll
        for (int mt = 0; mt < 4; ++mt)
#pragma unroll
            for (int nt = 0; nt < 4; ++nt)
                MMA_16816(acc[mt][nt], ahi[mt], blo[nt]);
    }

    // --- epilogue: d2 = q2 + k2 - 2*qk; out = exp(-0.5*max(d2,0))
    const float* q2p = g_q2 + h * NSEQ + row0;
    const float* k2p = g_k2 + h * NSEQ + col0;
    float* outh = out + (size_t)h * NSEQ * NSEQ;

#pragma unroll
    for (int mt = 0; mt < 4; ++mt) {
        const int rA = wm * 64 + mt * 16 + (lane >> 2);
        const int rB = rA + 8;
        const float q2a = q2p[rA];
        const float q2b = q2p[rB];
        float* orowA = outh + (size_t)(row0 + rA) * NSEQ + col0;
        float* orowB = outh + (size_t)(row0 + rB) * NSEQ + col0;
#pragma unroll
        for (int nt = 0; nt < 4; ++nt) {
            const int c = wn * 32 + nt * 8 + (lane & 3) * 2;
            const float k2a = k2p[c];
            const float k2b = k2p[c + 1];
            const float* v = acc[mt][nt];
            float2 oA, oB;
            oA.x = __expf(-0.5f * fmaxf(fmaf(-2.f, v[0], q2a + k2a), 0.f));
            oA.y = __expf(-0.5f * fmaxf(fmaf(-2.f, v[1], q2a + k2b), 0.f));
            oB.x = __expf(-0.5f * fmaxf(fmaf(-2.f, v[2], q2b + k2a), 0.f));
            oB.y = __expf(-0.5f * fmaxf(fmaf(-2.f, v[3], q2b + k2b), 0.f));
            *reinterpret_cast<float2*>(orowA + c) = oA;
            *reinterpret_cast<float2*>(orowB + c) = oB;
        }
    }
}

// ---------------------------------------------------------------------------
extern "C" void kernel_launch(void* const* d_in, const int* in_sizes, int n_in,
                              void* d_out, int out_size) {
    const float* q = (const float*)d_in[0];
    const float* k = (const float*)d_in[1];
    float* out = (float*)d_out;

    cudaFuncSetAttribute(hept_mma_kernel,
                         cudaFuncAttributeMaxDynamicSharedMemorySize, SM_ALLOC);

    dim3 ngrid((HEADS * NSEQ + 255) / 256, 2, 1);
    hept_norms_kernel<<<ngrid, 256>>>(q, k);

    const int total4 = HEADS * NSEQ * DDIM / 4;
    dim3 sgrid((total4 + 255) / 256, 2, 1);
    hept_split_kernel<<<sgrid, 256>>>(q, k);

    dim3 mgrid(NSEQ / TILE, NSEQ / TILE, HEADS);
    hept_mma_kernel<<<mgrid, 256, SM_ALLOC>>>(out);
}